// round 17
// baseline (speedup 1.0000x reference)
#include <cuda_runtime.h>
#include <cuda_fp16.h>
#include <cstdint>
#include <math.h>

#define BATCH 4096
#define HID 512
#define SEQLEN 7
#define SEQF 160                 // conv feature dim (no padding; 160 % 32 == 0)
#define G4 2048
#define NCLS 256
#define BT (BATCH * SEQLEN)
#define KL1 (HID + SEQF)         // 672: fused [h1 | x_t] K for layer 1

// ---------------------------------------------------------------------------
// scratch
// ---------------------------------------------------------------------------
__device__ __align__(16) __half d_seq[BT * SEQF];
__device__ __align__(16) __half d_cat0[BATCH * 1024];
__device__ __align__(16) __half d_cat1[BATCH * 1024];
__device__ __align__(16) float d_c1[BATCH * HID];
__device__ __align__(16) float d_c2[BATCH * HID];
// weights: transposed [N,K], gate-permuted cols (col' = 4j+g), fp16
__device__ __align__(16) __half d_UWp[G4 * KL1];    // [U1;W1] fused along K
__device__ __align__(16) __half d_WCp[G4 * 1024];   // [W2;U2]
__device__ __align__(16) __half d_FCt[NCLS * HID];
__device__ __align__(16) float d_pb1[G4];
__device__ __align__(16) float d_pb2[G4];

// ---------------------------------------------------------------------------
__global__ void init_state(uint32_t* __restrict__ c0, uint32_t* __restrict__ c1h,
                           float* __restrict__ c1, float* __restrict__ c2) {
    int i = blockIdx.x * blockDim.x + threadIdx.x;
    c0[i] = 0u;
    c1h[i] = 0u;
    c1[i] = 0.0f;
    c2[i] = 0.0f;
}

// ---------------------------------------------------------------------------
// weight prep: transpose + gate-permute + fp16, fused [U1;W1], + biases
// ---------------------------------------------------------------------------
#define PREP_UW (G4 * KL1)
#define PREP_WC (G4 * 1024)
#define PREP_FC (NCLS * HID)
#define PREP_PB (2 * G4)
#define PREP_TOTAL (PREP_UW + PREP_WC + PREP_FC + PREP_PB)

__global__ void prep_weights(const float* __restrict__ W1, const float* __restrict__ U1,
                             const float* __restrict__ W2, const float* __restrict__ U2,
                             const float* __restrict__ FC,
                             const float* __restrict__ b1, const float* __restrict__ b2,
                             __half* __restrict__ uwp, __half* __restrict__ wcp,
                             __half* __restrict__ fct,
                             float* __restrict__ pb1, float* __restrict__ pb2) {
    int i = blockIdx.x * blockDim.x + threadIdx.x;
    if (i >= PREP_TOTAL) return;
    if (i >= PREP_UW + PREP_WC + PREP_FC) {
        int o = i - (PREP_UW + PREP_WC + PREP_FC);
        int which = o >> 11;
        int np = o & 2047;
        int src = (np & 3) * HID + (np >> 2);
        if (which == 0) pb1[np] = b1[src]; else pb2[np] = b2[src];
        return;
    }
    float v;
    __half* dst;
    int o;
    if (i < PREP_UW) {
        o = i;
        int np = o / KL1, k = o % KL1;
        int n = (np & 3) * HID + (np >> 2);
        v = (k < HID) ? U1[(size_t)k * G4 + n] : W1[(size_t)(k - HID) * G4 + n];
        dst = uwp;
    } else if (i < PREP_UW + PREP_WC) {
        o = i - PREP_UW;
        int np = o >> 10, k = o & 1023;
        int n = (np & 3) * HID + (np >> 2);
        v = (k < HID) ? W2[(size_t)k * G4 + n] : U2[(size_t)(k - HID) * G4 + n];
        dst = wcp;
    } else {
        o = i - PREP_UW - PREP_WC;
        int n = o >> 9, k = o & 511;
        v = FC[(size_t)k * NCLS + n];
        dst = fct;
    }
    dst[o] = __float2half_rn(v);
}

// ---------------------------------------------------------------------------
// fused conv1+pool1+conv2+pool2 -> seq fp16 [B,7,160]; one block per sample.
// ---------------------------------------------------------------------------
__global__ __launch_bounds__(256) void conv12_pool(
    const float* __restrict__ x,
    const float* __restrict__ w1, const float* __restrict__ b1,
    const float* __restrict__ w2, const float* __restrict__ b2,
    __half* __restrict__ sh) {
    __shared__ float sIn[15 * 80 * 3];
    __shared__ float sW1[7 * 3 * 3 * 10];
    __shared__ float sP[9 * 26 * 10];
    __shared__ float sW2[3 * 3 * 10 * 20];
    int b = blockIdx.x;
    const float* xb = x + (size_t)b * 3600;
    for (int i = threadIdx.x; i < 3600; i += 256) sIn[i] = xb[i];
    for (int i = threadIdx.x; i < 630; i += 256) sW1[i] = w1[i];
    for (int i = threadIdx.x; i < 1800; i += 256) sW2[i] = w2[i];
    __syncthreads();

    for (int item = threadIdx.x; item < 9 * 260; item += 256) {
        int r = item / 260;
        int rem = item - r * 260;
        int p = rem / 10, co = rem - p * 10;
        float best = -1e30f;
#pragma unroll
        for (int dx = 0; dx < 3; dx++) {
            int cw = p * 3 + dx;
            float acc = 0.0f;
#pragma unroll
            for (int kh = 0; kh < 7; kh++)
#pragma unroll
                for (int kw = 0; kw < 3; kw++)
#pragma unroll
                    for (int ci = 0; ci < 3; ci++)
                        acc += sIn[(r + kh) * 240 + (cw + kw) * 3 + ci] *
                               sW1[((kh * 3 + kw) * 3 + ci) * 10 + co];
            best = fmaxf(best, acc);
        }
        sP[(r * 26 + p) * 10 + co] = fmaxf(best + b1[co], 0.0f);
    }
    __syncthreads();

    for (int item = threadIdx.x; item < 7 * 160; item += 256) {
        int r = item / 160;
        int f = item - r * 160;
        int p = f / 20, co = f - p * 20;
        float best = -1e30f;
#pragma unroll
        for (int dx = 0; dx < 3; dx++) {
            int cw = p * 3 + dx;
            float acc = 0.0f;
#pragma unroll
            for (int kh = 0; kh < 3; kh++)
#pragma unroll
                for (int kw = 0; kw < 3; kw++)
#pragma unroll
                    for (int ci = 0; ci < 10; ci++)
                        acc += sP[((r + kh) * 26 + (cw + kw)) * 10 + ci] *
                               sW2[((kh * 3 + kw) * 10 + ci) * 20 + co];
            best = fmaxf(best, acc);
        }
        float v = fmaxf(best + b2[co], 0.0f);
        sh[(size_t)(b * 7 + r) * SEQF + f] = __float2half_rn(v);
    }
}

// ---------------------------------------------------------------------------
// dual-job fp16 1-pass GEMM with split-K A source (A for k<KA, A2 after):
// tile 128x64, 256 thr (4x2 warps of 32x32), 3-stage cp.async ring, 4 CTAs/SM.
// gate mode = fused LSTM epilogue staged through SMEM.
// ---------------------------------------------------------------------------
struct GemmJob {
    const __half* A; int lda; int KA;     // first A segment (K multiple of 32)
    const __half* A2; int lda2; int K2;   // optional second A segment
    const __half* B; int ldb;             // B [N, KA+K2]
    const float* bias;
    float* C; int ldc;
    int relu, gate;
    float* cbuf;
    __half* hout; int hoff;
    int nx;                               // N tiles (N = nx*64)
};

#define ROWB 80
#define A_TILE_B (128 * ROWB)             // 10240
#define B_TILE_B (64 * ROWB)              // 5120
#define STAGE_B (A_TILE_B + B_TILE_B)     // 15360
#define GSM_BYTES 46080                   // 3*STAGE_B; >= epi 128*68*4=34816
#define EPI_PITCH 68
#define NTHR 256

__device__ __forceinline__ uint32_t smem_u32(const void* p) {
    uint32_t a;
    asm("{ .reg .u64 t; cvta.to.shared.u64 t, %1; cvt.u32.u64 %0, t; }" : "=r"(a) : "l"(p));
    return a;
}
__device__ __forceinline__ void cp_async16(uint32_t sa, const void* gaddr) {
    asm volatile("cp.async.cg.shared.global [%0], [%1], 16;" :: "r"(sa), "l"(gaddr) : "memory");
}
__device__ __forceinline__ void ldmx4(uint32_t* r, uint32_t sa) {
    asm volatile("ldmatrix.sync.aligned.m8n8.x4.shared.b16 {%0,%1,%2,%3}, [%4];"
                 : "=r"(r[0]), "=r"(r[1]), "=r"(r[2]), "=r"(r[3]) : "r"(sa));
}
__device__ __forceinline__ void mma_f16(float* c, const uint32_t* a, uint32_t b0, uint32_t b1) {
    asm volatile(
        "mma.sync.aligned.m16n8k16.row.col.f32.f16.f16.f32 "
        "{%0,%1,%2,%3}, {%4,%5,%6,%7}, {%8,%9}, {%0,%1,%2,%3};"
        : "+f"(c[0]), "+f"(c[1]), "+f"(c[2]), "+f"(c[3])
        : "r"(a[0]), "r"(a[1]), "r"(a[2]), "r"(a[3]), "r"(b0), "r"(b1));
}
__device__ __forceinline__ float sigacc(float x) { return 1.0f / (1.0f + expf(-x)); }

__global__ __launch_bounds__(NTHR, 4) void gemm_dual(int M, GemmJob j0, GemmJob j1) {
    extern __shared__ char smem[];
    uint32_t sb0 = smem_u32(smem);
    int tid = threadIdx.x;
    int lane = tid & 31;
    int warp = tid >> 5;
    int wm = warp >> 1;
    int wn = warp & 1;
    int gid = lane >> 2;
    int tig = lane & 3;
    int lane15 = lane & 15;
    int halfsel = (lane >> 4) << 4;

    int isj0 = (int)(blockIdx.x < (unsigned)j0.nx);
    GemmJob j = isj0 ? j0 : j1;
    int bn = (isj0 ? blockIdx.x : blockIdx.x - j0.nx) * 64;
    int bm = blockIdx.y * 128;

    const __half* A0 = j.A + (size_t)bm * j.lda;
    const __half* A2 = j.A2 ? (j.A2 + (size_t)bm * j.lda2) : nullptr;
    const __half* B0 = j.B + (size_t)bn * j.ldb;
    int lda = j.lda, lda2 = j.lda2, ldb = j.ldb;
    int KA = j.KA;

    float acc[2][4][4];
#pragma unroll
    for (int i = 0; i < 2; i++)
#pragma unroll
        for (int jj = 0; jj < 4; jj++)
#pragma unroll
            for (int r = 0; r < 4; r++) acc[i][jj][r] = 0.0f;

    int nst = (KA + j.K2) >> 5;

    int cp_row = tid >> 2, cp_c4 = tid & 3;

#define ISSUE_STAGE(kt, slot) do {                                             \
        if ((kt) < nst) {                                                      \
            uint32_t st = sb0 + (slot) * STAGE_B;                              \
            int k0 = (kt) << 5;                                                \
            const __half* Ap; int ldA; int ko;                                 \
            if (k0 < KA) { Ap = A0; ldA = lda; ko = k0; }                      \
            else { Ap = A2; ldA = lda2; ko = k0 - KA; }                        \
            uint32_t sa = st + cp_row * ROWB + cp_c4 * 16;                     \
            cp_async16(sa, Ap + (size_t)cp_row * ldA + ko + cp_c4 * 8);        \
            cp_async16(sa + 64 * ROWB,                                         \
                       Ap + (size_t)(cp_row + 64) * ldA + ko + cp_c4 * 8);     \
            cp_async16(st + A_TILE_B + cp_row * ROWB + cp_c4 * 16,             \
                       B0 + (size_t)cp_row * ldb + k0 + cp_c4 * 8);            \
        }                                                                      \
        asm volatile("cp.async.commit_group;" ::: "memory");                   \
    } while (0)

    ISSUE_STAGE(0, 0);
    ISSUE_STAGE(1, 1);

    int slot = 0, slot2 = 2;
    for (int kt = 0; kt < nst; kt++) {
        asm volatile("cp.async.wait_group 1;" ::: "memory");
        __syncthreads();
        ISSUE_STAGE(kt + 2, slot2);

        uint32_t st = sb0 + slot * STAGE_B;
        uint32_t aAddr = st + (uint32_t)((wm * 32 + lane15) * ROWB) + halfsel;
        uint32_t bAddr = st + A_TILE_B + (uint32_t)((wn * 32 + lane15) * ROWB) + halfsel;

#pragma unroll
        for (int k16 = 0; k16 < 2; k16++) {
            uint32_t kb = k16 * 32;
            uint32_t af[2][4], bf[2][4];
            ldmx4(af[0], aAddr + kb);
            ldmx4(af[1], aAddr + 16 * ROWB + kb);
            ldmx4(bf[0], bAddr + kb);
            ldmx4(bf[1], bAddr + 16 * ROWB + kb);
#pragma unroll
            for (int nb = 0; nb < 2; nb++) {
#pragma unroll
                for (int hf = 0; hf < 2; hf++) {
                    int na = nb * 2 + hf;
#pragma unroll
                    for (int ma = 0; ma < 2; ma++)
                        mma_f16(acc[ma][na], af[ma], bf[nb][hf], bf[nb][2 + hf]);
                }
            }
        }
        slot = (slot == 2) ? 0 : slot + 1;
        slot2 = (slot2 == 2) ? 0 : slot2 + 1;
    }
    __syncthreads();

    // ---- epilogue ----
    if (j.gate) {
        float* sg = (float*)smem;
#pragma unroll
        for (int ma = 0; ma < 2; ma++) {
#pragma unroll
            for (int na = 0; na < 4; na++) {
                int rl = wm * 32 + ma * 16 + gid;
                int cl = wn * 32 + na * 8 + 2 * tig;
                int col0 = bn + cl;
                float bb0 = j.bias[col0], bb1 = j.bias[col0 + 1];
                *(float2*)&sg[rl * EPI_PITCH + cl] =
                    make_float2(acc[ma][na][0] + bb0, acc[ma][na][1] + bb1);
                *(float2*)&sg[(rl + 8) * EPI_PITCH + cl] =
                    make_float2(acc[ma][na][2] + bb0, acc[ma][na][3] + bb1);
            }
        }
        __syncthreads();
        int jb = bn >> 2;
#pragma unroll
        for (int it = 0; it < 8; it++) {
            int idx = it * NTHR + tid;
            int rl = idx >> 4, jl = idx & 15;
            float4 g = *(const float4*)&sg[rl * EPI_PITCH + jl * 4];
            int grow = bm + rl;
            int jcol = jb + jl;
            size_t cidx = (size_t)grow * HID + jcol;
            float cv = sigacc(g.y) * j.cbuf[cidx] + sigacc(g.x) * tanhf(g.z);
            j.cbuf[cidx] = cv;
            float h = sigacc(g.w) * tanhf(cv);
            j.hout[(size_t)grow * 1024 + j.hoff + jcol] = __float2half_rn(h);
        }
    } else {
#pragma unroll
        for (int ma = 0; ma < 2; ma++) {
#pragma unroll
            for (int na = 0; na < 4; na++) {
                int row0 = bm + wm * 32 + ma * 16 + gid;
                int col = bn + wn * 32 + na * 8 + 2 * tig;
                float v0 = acc[ma][na][0], v1 = acc[ma][na][1];
                float v2 = acc[ma][na][2], v3 = acc[ma][na][3];
                if (j.bias) {
                    float bb0 = j.bias[col], bb1 = j.bias[col + 1];
                    v0 += bb0; v1 += bb1; v2 += bb0; v3 += bb1;
                }
                if (j.relu) {
                    v0 = fmaxf(v0, 0.0f); v1 = fmaxf(v1, 0.0f);
                    v2 = fmaxf(v2, 0.0f); v3 = fmaxf(v3, 0.0f);
                }
                *(float2*)(j.C + (size_t)row0 * j.ldc + col) = make_float2(v0, v1);
                *(float2*)(j.C + (size_t)(row0 + 8) * j.ldc + col) = make_float2(v2, v3);
            }
        }
    }
#undef ISSUE_STAGE
}

// ---------------------------------------------------------------------------
// launch
// ---------------------------------------------------------------------------
extern "C" void kernel_launch(void* const* d_in, const int* in_sizes, int n_in,
                              void* d_out, int out_size) {
    const float* x = (const float*)d_in[0];
    const float* c1w = (const float*)d_in[1];
    const float* c1b = (const float*)d_in[2];
    const float* c2w = (const float*)d_in[3];
    const float* c2b = (const float*)d_in[4];
    const float* W1 = (const float*)d_in[5];
    const float* U1 = (const float*)d_in[6];
    const float* b1 = (const float*)d_in[7];
    const float* W2 = (const float*)d_in[8];
    const float* U2 = (const float*)d_in[9];
    const float* b2 = (const float*)d_in[10];
    const float* fcw = (const float*)d_in[11];
    const float* fcb = (const float*)d_in[12];
    float* out = (float*)d_out;

    float *c1, *c2, *pb1, *pb2;
    __half *seqh;
    __half *cat[2];
    __half *uwp, *wcp, *fct;
    cudaGetSymbolAddress((void**)&c1, d_c1);
    cudaGetSymbolAddress((void**)&c2, d_c2);
    cudaGetSymbolAddress((void**)&pb1, d_pb1);
    cudaGetSymbolAddress((void**)&pb2, d_pb2);
    cudaGetSymbolAddress((void**)&seqh, d_seq);
    cudaGetSymbolAddress((void**)&cat[0], d_cat0);
    cudaGetSymbolAddress((void**)&cat[1], d_cat1);
    cudaGetSymbolAddress((void**)&uwp, d_UWp);
    cudaGetSymbolAddress((void**)&wcp, d_WCp);
    cudaGetSymbolAddress((void**)&fct, d_FCt);

    cudaFuncSetAttribute(gemm_dual, cudaFuncAttributeMaxDynamicSharedMemorySize, GSM_BYTES);

    init_state<<<(BATCH * 1024 / 2) / 256, 256>>>(
        (uint32_t*)cat[0], (uint32_t*)cat[1], c1, c2);
    prep_weights<<<(PREP_TOTAL + 255) / 256, 256>>>(W1, U1, W2, U2, fcw, b1, b2,
                                                    uwp, wcp, fct, pb1, pb2);
    conv12_pool<<<BATCH, 256>>>(x, c1w, c1b, c2w, c2b, seqh);

    GemmJob nil{};
    nil.nx = 0;

    // layer 1 (t): gates([h1_{t-1} | x_t] @ [U1;W1]) ; reads cat[t&1],
    // writes h1_t -> cat[1-(t&1)][0:512]
    auto L1 = [&](int t) {
        GemmJob jb{};
        int p = t & 1;
        jb.A = cat[p]; jb.lda = 1024; jb.KA = HID;
        jb.A2 = seqh + t * SEQF; jb.lda2 = SEQLEN * SEQF; jb.K2 = SEQF;
        jb.B = uwp; jb.ldb = KL1;
        jb.bias = pb1;
        jb.C = nullptr; jb.ldc = 0; jb.relu = 0; jb.gate = 1;
        jb.cbuf = c1; jb.hout = cat[1 - p]; jb.hoff = 0;
        jb.nx = G4 / 64;
        return jb;
    };
    // layer 2 (t): gates([h1_t | h2_{t-1}] @ [W2;U2]) ; reads cat[1-(t&1)],
    // writes h2_t -> cat[t&1][512:1024]
    auto L2 = [&](int t) {
        GemmJob jb{};
        int p = t & 1;
        jb.A = cat[1 - p]; jb.lda = 1024; jb.KA = 1024;
        jb.A2 = nullptr; jb.lda2 = 0; jb.K2 = 0;
        jb.B = wcp; jb.ldb = 1024;
        jb.bias = pb2;
        jb.C = nullptr; jb.ldc = 0; jb.relu = 0; jb.gate = 1;
        jb.cbuf = c2; jb.hout = cat[p]; jb.hoff = HID;
        jb.nx = G4 / 64;
        return jb;
    };

    // L1(0)
    {
        GemmJob jb = L1(0);
        dim3 g(jb.nx, BATCH / 128);
        gemm_dual<<<g, NTHR, GSM_BYTES>>>(BATCH, jb, nil);
    }
    // combined phases: {L2(t) || L1(t+1)} for t = 0..5
    for (int t = 0; t < SEQLEN - 1; t++) {
        GemmJob ja = L2(t);
        GemmJob jb = L1(t + 1);
        dim3 g(ja.nx + jb.nx, BATCH / 128);
        gemm_dual<<<g, NTHR, GSM_BYTES>>>(BATCH, ja, jb);
    }
    // L2(6)
    {
        GemmJob jb = L2(SEQLEN - 1);
        dim3 g(jb.nx, BATCH / 128);
        gemm_dual<<<g, NTHR, GSM_BYTES>>>(BATCH, jb, nil);
    }

    // FC head: relu(h2 @ fc_w + fc_b); final h2 in cat[(SEQLEN-1)&1] = cat[0]
    {
        GemmJob jb{};
        int pf = (SEQLEN - 1) & 1;
        jb.A = cat[pf] + HID; jb.lda = 1024; jb.KA = HID;
        jb.A2 = nullptr; jb.lda2 = 0; jb.K2 = 0;
        jb.B = fct; jb.ldb = HID;
        jb.bias = fcb;
        jb.C = out; jb.ldc = NCLS; jb.relu = 1; jb.gate = 0;
        jb.cbuf = nullptr; jb.hout = nullptr; jb.hoff = 0;
        jb.nx = NCLS / 64;
        dim3 g(jb.nx, BATCH / 128);
        gemm_dual<<<g, NTHR, GSM_BYTES>>>(BATCH, jb, nil);
    }
}